// round 8
// baseline (speedup 1.0000x reference)
#include <cuda_runtime.h>
#include <math.h>

#define B_   8192
#define F_   32
#define P_   512
#define H_   256
#define BM   16        // rows per CTA
#define KC   16        // K-chunk for W1 staging (16 -> wreg[8], fits 64 regs)
#define NT   256       // threads per CTA

#define PITCH2 257     // pitch (in float2) for paired-W1 smem chunk

// dynamic smem layout (floats):
//   xn    : BM * P_            = 8192   (32 KB)
//   sW2   : (KC/2) * PITCH2 *2 = 4112   (16.4 KB, float2 pairs)
//   wnorm : BM * F_            = 512
//   red   : BM * 8             = 128
//   slen  : BM (ints)          = 16
#define SMEM_FLOATS (BM * P_ + (KC/2) * PITCH2 * 2 + BM * F_ + BM * 8 + BM)

// packed fp32x2 FMA: d = a*b + d elementwise on two fp32 lanes
__device__ __forceinline__ void ffma2(double& acc, double x, double w) {
    asm("fma.rn.f32x2 %0, %1, %2, %0;"
        : "+l"(*reinterpret_cast<unsigned long long*>(&acc))
        : "l"(*reinterpret_cast<unsigned long long*>(&x)),
          "l"(*reinterpret_cast<unsigned long long*>(&w)));
}

__global__ __launch_bounds__(NT, 4)
void physchem_fused(const float* __restrict__ phys,
                    const float* __restrict__ ratios,
                    const int*   __restrict__ lengths,
                    const float* __restrict__ ln_gamma,
                    const float* __restrict__ ln_beta,
                    const float* __restrict__ W1,
                    const float* __restrict__ b1,
                    const float* __restrict__ W2,
                    const float* __restrict__ b2,
                    float*       __restrict__ out)
{
    extern __shared__ float sm[];
    float*  xn    = sm;                                   // [BM][P_]
    float2* sW2   = (float2*)(sm + BM * P_);              // [KC/2][PITCH2]
    float*  wnorm = sm + BM * P_ + (KC / 2) * PITCH2 * 2; // [BM][F_]
    float*  red   = wnorm + BM * F_;                      // [BM][8]
    int*    slen  = (int*)(red + BM * 8);                 // [BM]

    const int tid  = threadIdx.x;
    const int wid  = tid >> 5;
    const int lane = tid & 31;
    const int b0   = blockIdx.x * BM;

    // ---------- Phase A0: normalized weights (warp w -> rows 2w, 2w+1) ----------
    #pragma unroll
    for (int rr = 0; rr < 2; rr++) {
        const int r = wid * 2 + rr;
        const int b = b0 + r;
        const int len = lengths[b];
        if (lane == 0) slen[r] = len;
        float rv = (lane < len) ? ratios[b * F_ + lane] : 0.0f;
        float s = rv;
        #pragma unroll
        for (int o = 16; o > 0; o >>= 1) s += __shfl_xor_sync(0xffffffffu, s, o);
        wnorm[r * F_ + lane] = rv / (s + 1e-8f);  // zero for lane >= len
    }
    __syncthreads();

    // ---------- Phase A1: weighted mix. Warp w owns p-slice [64w, 64w+64). ------
    // Every warp does identical Sum(len) work -> no intra-CTA straggler.
    const int p2 = wid * 32 + lane;                 // float2 index within row
    for (int r = 0; r < BM; r++) {
        const int len = slen[r];
        const int b   = b0 + r;
        const float2* pp = (const float2*)phys + ((size_t)b * (F_ * P_) >> 1) + p2;
        const float* wr = wnorm + r * F_;
        float ax = 0.0f, ay = 0.0f;
        const int f4 = (len + 3) & ~3;              // wnorm zero-padded past len
        for (int f = 0; f < f4; f += 4) {
            const float w0  = wr[f + 0];
            const float w1  = wr[f + 1];
            const float w2_ = wr[f + 2];
            const float w3  = wr[f + 3];
            float2 v0 = pp[(f + 0) * (P_ / 2)];
            float2 v1 = pp[(f + 1) * (P_ / 2)];
            float2 v2 = pp[(f + 2) * (P_ / 2)];
            float2 v3 = pp[(f + 3) * (P_ / 2)];
            ax += w0 * v0.x;  ay += w0 * v0.y;
            ax += w1 * v1.x;  ay += w1 * v1.y;
            ax += w2_ * v2.x; ay += w2_ * v2.y;
            ax += w3 * v3.x;  ay += w3 * v3.y;
        }
        ((float2*)(xn + r * P_))[p2] = make_float2(ax, ay);
    }
    __syncthreads();

    // ---------- Phase A2: LayerNorm in-place (warp w -> rows 2w, 2w+1) ----------
    #pragma unroll
    for (int rr = 0; rr < 2; rr++) {
        const int r = wid * 2 + rr;
        float4 vv[4];
        float s = 0.0f, s2 = 0.0f;
        #pragma unroll
        for (int i = 0; i < 4; i++) {
            vv[i] = ((const float4*)(xn + r * P_))[lane + 32 * i];
            s  += vv[i].x + vv[i].y + vv[i].z + vv[i].w;
            s2 += vv[i].x * vv[i].x + vv[i].y * vv[i].y
                + vv[i].z * vv[i].z + vv[i].w * vv[i].w;
        }
        #pragma unroll
        for (int o = 16; o > 0; o >>= 1) {
            s  += __shfl_xor_sync(0xffffffffu, s,  o);
            s2 += __shfl_xor_sync(0xffffffffu, s2, o);
        }
        const float mu   = s * (1.0f / P_);
        const float var  = fmaxf(s2 * (1.0f / P_) - mu * mu, 0.0f);
        const float rstd = rsqrtf(var + 1e-5f);
        #pragma unroll
        for (int i = 0; i < 4; i++) {
            const int vi = lane + 32 * i;
            float4 g  = ((const float4*)ln_gamma)[vi];
            float4 be = ((const float4*)ln_beta)[vi];
            float4 o4;
            o4.x = (vv[i].x - mu) * rstd * g.x + be.x;
            o4.y = (vv[i].y - mu) * rstd * g.y + be.y;
            o4.z = (vv[i].z - mu) * rstd * g.z + be.z;
            o4.w = (vv[i].w - mu) * rstd * g.w + be.w;
            ((float4*)(xn + r * P_))[vi] = o4;
        }
    }
    __syncthreads();

    // ---------- Phase B: x @ W1^T with packed fp32x2 FMAs ----------
    // Thread tid owns output column j = tid. hacc2[r] = two fp32 partial sums.
    double hacc2[BM];
    #pragma unroll
    for (int r = 0; r < BM; r++) hacc2[r] = 0.0;

    for (int kk = 0; kk < P_; kk += KC) {
        // stage W1[:, kk:kk+KC] as k-pairs: sW2[kp][j] = (W1[j][2kp], W1[j][2kp+1])
        #pragma unroll
        for (int t = 0; t < (H_ * KC) / (NT * 4); t++) {   // 4 iters
            const int e = 4 * tid + t * NT * 4;
            const int j = e >> 4;                 // 0..255
            const int k = e & 15;                 // multiple of 4
            float4 v = *(const float4*)(W1 + j * P_ + kk + k);
            float2* dst = sW2 + (k >> 1) * PITCH2 + j;
            dst[0]      = make_float2(v.x, v.y);
            dst[PITCH2] = make_float2(v.z, v.w);
        }
        __syncthreads();

        // this thread's 8 weight pairs for the chunk
        double wreg[KC / 2];
        #pragma unroll
        for (int kp = 0; kp < KC / 2; kp++)
            wreg[kp] = *(const double*)(sW2 + kp * PITCH2 + tid);

        #pragma unroll
        for (int r = 0; r < BM; r++) {
            const double2* xr = (const double2*)(xn + r * P_ + kk);
            #pragma unroll
            for (int q = 0; q < KC / 4; q++) {    // 4 x LDS.128 broadcast
                double2 v = xr[q];
                ffma2(hacc2[r], v.x, wreg[2 * q]);
                ffma2(hacc2[r], v.y, wreg[2 * q + 1]);
            }
        }
        __syncthreads();
    }

    // ---------- Epilogue: ReLU, dot with W2, reduce, nan_to_num ----------
    const float w2  = W2[tid];
    const float bb1 = b1[tid];
    #pragma unroll
    for (int r = 0; r < BM; r++) {
        float2 p = *reinterpret_cast<float2*>(&hacc2[r]);
        float h = p.x + p.y + bb1;
        h = fmaxf(h, 0.0f);
        float v = h * w2;
        #pragma unroll
        for (int o = 16; o > 0; o >>= 1) v += __shfl_xor_sync(0xffffffffu, v, o);
        if (lane == 0) red[r * 8 + wid] = v;
    }
    __syncthreads();

    if (tid < BM) {
        float y = b2[0];
        #pragma unroll
        for (int w = 0; w < 8; w++) y += red[tid * 8 + w];
        if (isnan(y)) y = 0.0f;
        else if (isinf(y)) y = (y > 0.0f) ? 3.4028234663852886e38f : -3.4028234663852886e38f;
        out[b0 + tid] = y;
    }
}

extern "C" void kernel_launch(void* const* d_in, const int* in_sizes, int n_in,
                              void* d_out, int out_size)
{
    const float* phys     = (const float*)d_in[0];
    const float* ratios   = (const float*)d_in[1];
    const int*   lengths  = (const int*)  d_in[2];
    const float* ln_gamma = (const float*)d_in[3];
    const float* ln_beta  = (const float*)d_in[4];
    const float* W1       = (const float*)d_in[5];
    const float* b1       = (const float*)d_in[6];
    const float* W2       = (const float*)d_in[7];
    const float* b2       = (const float*)d_in[8];
    float* out = (float*)d_out;

    const int smem_bytes = SMEM_FLOATS * (int)sizeof(float);
    cudaFuncSetAttribute(physchem_fused,
                         cudaFuncAttributeMaxDynamicSharedMemorySize, smem_bytes);

    dim3 grid(B_ / BM);
    dim3 block(NT);
    physchem_fused<<<grid, block, smem_bytes>>>(
        phys, ratios, lengths, ln_gamma, ln_beta, W1, b1, W2, b2, out);
}

// round 12
// speedup vs baseline: 1.4179x; 1.4179x over previous
#include <cuda_runtime.h>
#include <math.h>
#include <stdint.h>

#define B_   8192
#define F_   32
#define P_   512
#define H_   256
#define BM   16        // rows per CTA
#define KC   32        // K-chunk for W1 staging (R4 best config)
#define NT   256       // threads per CTA

#define PITCH2 257     // pitch (in float2) for paired-W1 smem chunk

// union region: phase A (ring 4096 + fidx 512 + wflat 512 + wnorm 512 + slen 16)
//               phase B (sW2 = 16*257*2 = 8224 floats)  -> size 8448 floats
#define UNI_FLOATS 8448
// smem (floats): xn 8192 + union 8448 + red 128
#define SMEM_FLOATS (BM * P_ + UNI_FLOATS + BM * 8)

// ---- cp.async helpers (LDGSTS, 8B) ----
__device__ __forceinline__ void cp_async8(uint32_t dst_smem, const void* src) {
    asm volatile("cp.async.ca.shared.global [%0], [%1], 8;" :: "r"(dst_smem), "l"(src));
}
__device__ __forceinline__ void cp_commit() {
    asm volatile("cp.async.commit_group;" ::: "memory");
}
template <int N>
__device__ __forceinline__ void cp_wait() {
    asm volatile("cp.async.wait_group %0;" :: "n"(N) : "memory");
}

// packed fp32x2 FMA
__device__ __forceinline__ void ffma2(double& acc, double x, double w) {
    asm("fma.rn.f32x2 %0, %1, %2, %0;"
        : "+l"(*reinterpret_cast<unsigned long long*>(&acc))
        : "l"(*reinterpret_cast<unsigned long long*>(&x)),
          "l"(*reinterpret_cast<unsigned long long*>(&w)));
}

__global__ __launch_bounds__(NT, 3)
void physchem_fused(const float* __restrict__ phys,
                    const float* __restrict__ ratios,
                    const int*   __restrict__ lengths,
                    const float* __restrict__ ln_gamma,
                    const float* __restrict__ ln_beta,
                    const float* __restrict__ W1,
                    const float* __restrict__ b1,
                    const float* __restrict__ W2,
                    const float* __restrict__ b2,
                    float*       __restrict__ out)
{
    extern __shared__ float sm[];
    float*  xn    = sm;                          // [BM][P_]
    float*  uni   = sm + BM * P_;                // union region
    float*  red   = uni + UNI_FLOATS;            // [BM][8]
    // phase-A view of union region:
    float*  ring  = uni;                         // 8 warps * 8 slots * 64 floats
    int*    fidx  = (int*)(uni + 4096);          // [512]
    float*  wflat = uni + 4608;                  // [512]
    float*  wnorm = uni + 5120;                  // [BM][F_]
    int*    slen  = (int*)(uni + 5632);          // [BM]
    // phase-B view:
    float2* sW2   = (float2*)uni;                // [KC/2][PITCH2]

    const int tid  = threadIdx.x;
    const int wid  = tid >> 5;
    const int lane = tid & 31;
    const int b0   = blockIdx.x * BM;

    // ---------- A0: normalized weights + lengths (warp w -> rows 2w, 2w+1) ------
    #pragma unroll
    for (int rr = 0; rr < 2; rr++) {
        const int r = wid * 2 + rr;
        const int b = b0 + r;
        const int len = lengths[b];
        if (lane == 0) slen[r] = len;
        float rv = (lane < len) ? ratios[b * F_ + lane] : 0.0f;
        float s = rv;
        #pragma unroll
        for (int o = 16; o > 0; o >>= 1) s += __shfl_xor_sync(0xffffffffu, s, o);
        wnorm[r * F_ + lane] = rv / (s + 1e-8f);
    }
    __syncthreads();

    // ---------- A0b: prefix scan of slen (each warp, locally) -------------------
    int lv = (lane < BM) ? slen[lane] : 0;
    int inc = lv;
    #pragma unroll
    for (int o = 1; o < BM; o <<= 1) {
        int u = __shfl_up_sync(0xffffffffu, inc, o);
        if (lane >= o) inc += u;
    }
    const int T = __shfl_sync(0xffffffffu, inc, BM - 1);  // total fragments (>=16)
    const int excl = inc - lv;                             // exclusive offset

    // flattened (row, frag) list: warp w fills rows 2w, 2w+1
    #pragma unroll
    for (int rr = 0; rr < 2; rr++) {
        const int r   = wid * 2 + rr;
        const int len = __shfl_sync(0xffffffffu, lv,   r);
        const int off = __shfl_sync(0xffffffffu, excl, r);
        if (lane < len) {
            fidx[off + lane]  = (r << 8) | lane;
            wflat[off + lane] = wnorm[r * F_ + lane];
        }
    }
    __syncthreads();

    // ---------- A1: weighted mix, per-warp cp.async ring (8 slots, 7 in flight) --
    // Warp w owns p-slice [64w, 64w+64); lane owns 2 floats (8B) of each fragment.
    // Iter i: issue frag i+7 -> slot (i+7)&7  (never the slot read this iter),
    // wait_group 7 => frag i's group complete, read slot i&7.
    {
        const int p2 = wid * 32 + lane;                 // float2 index within row
        float* wring = ring + wid * 512;                // 8 slots * 64 floats
        uint32_t ring_u32;
        asm("{ .reg .u64 t; cvta.to.shared.u64 t, %1; cvt.u32.u64 %0, t; }"
            : "=r"(ring_u32) : "l"(wring + 2 * lane));

        const float* pbase = phys + (size_t)b0 * (F_ * P_) + wid * 64 + 2 * lane;

        // prologue: fragments 0..6 (T >= 16 always)
        #pragma unroll
        for (int j = 0; j < 7; j++) {
            const int rf = fidx[j];
            const float* src = pbase + ((size_t)((rf >> 8) * F_ + (rf & 255))) * P_;
            cp_async8(ring_u32 + j * 256, src);
            cp_commit();
        }

        int   cur_r = 0;
        float ax = 0.0f, ay = 0.0f;
        for (int i = 0; i < T; i++) {
            if (i + 7 < T) {
                const int rf = fidx[i + 7];
                const float* src = pbase + ((size_t)((rf >> 8) * F_ + (rf & 255))) * P_;
                cp_async8(ring_u32 + ((i + 7) & 7) * 256, src);
                cp_commit();
                cp_wait<7>();          // committed=8+i -> frags 0..i complete
            } else {
                cp_wait<0>();
            }
            const int r = fidx[i] >> 8;                 // warp-uniform broadcast
            if (r != cur_r) {
                ((float2*)(xn + cur_r * P_))[p2] = make_float2(ax, ay);
                ax = 0.0f; ay = 0.0f;
                cur_r = r;
            }
            const float w = wflat[i];                   // warp-uniform broadcast
            float2 v = *(float2*)(wring + (i & 7) * 64 + 2 * lane);
            ax += w * v.x;
            ay += w * v.y;
        }
        ((float2*)(xn + cur_r * P_))[p2] = make_float2(ax, ay);
    }
    __syncthreads();

    // ---------- A2: LayerNorm in-place (warp w -> rows 2w, 2w+1) ----------------
    #pragma unroll
    for (int rr = 0; rr < 2; rr++) {
        const int r = wid * 2 + rr;
        float4 vv[4];
        float s = 0.0f, s2 = 0.0f;
        #pragma unroll
        for (int i = 0; i < 4; i++) {
            vv[i] = ((const float4*)(xn + r * P_))[lane + 32 * i];
            s  += vv[i].x + vv[i].y + vv[i].z + vv[i].w;
            s2 += vv[i].x * vv[i].x + vv[i].y * vv[i].y
                + vv[i].z * vv[i].z + vv[i].w * vv[i].w;
        }
        #pragma unroll
        for (int o = 16; o > 0; o >>= 1) {
            s  += __shfl_xor_sync(0xffffffffu, s,  o);
            s2 += __shfl_xor_sync(0xffffffffu, s2, o);
        }
        const float mu   = s * (1.0f / P_);
        const float var  = fmaxf(s2 * (1.0f / P_) - mu * mu, 0.0f);
        const float rstd = rsqrtf(var + 1e-5f);
        #pragma unroll
        for (int i = 0; i < 4; i++) {
            const int vi = lane + 32 * i;
            float4 g  = ((const float4*)ln_gamma)[vi];
            float4 be = ((const float4*)ln_beta)[vi];
            float4 o4;
            o4.x = (vv[i].x - mu) * rstd * g.x + be.x;
            o4.y = (vv[i].y - mu) * rstd * g.y + be.y;
            o4.z = (vv[i].z - mu) * rstd * g.z + be.z;
            o4.w = (vv[i].w - mu) * rstd * g.w + be.w;
            ((float4*)(xn + r * P_))[vi] = o4;
        }
    }
    __syncthreads();

    // ---------- Phase B: x @ W1^T with packed fp32x2 FMAs (R4 config) ----------
    double hacc2[BM];
    #pragma unroll
    for (int r = 0; r < BM; r++) hacc2[r] = 0.0;

    for (int kk = 0; kk < P_; kk += KC) {
        // stage W1[:, kk:kk+KC] as k-pairs: sW2[kp][j] = (W1[j][2kp], W1[j][2kp+1])
        {
            const int base = 4 * tid;
            #pragma unroll
            for (int t = 0; t < (H_ * KC) / (NT * 4); t++) {   // 8 iters
                const int e = base + t * NT * 4;
                const int j = e >> 5;                 // 0..255
                const int k = e & 31;                 // multiple of 4
                float4 v = *(const float4*)(W1 + j * P_ + kk + k);
                float2* dst = sW2 + (k >> 1) * PITCH2 + j;
                dst[0]      = make_float2(v.x, v.y);
                dst[PITCH2] = make_float2(v.z, v.w);
            }
        }
        __syncthreads();

        double wreg[KC / 2];
        #pragma unroll
        for (int kp = 0; kp < KC / 2; kp++)
            wreg[kp] = *(const double*)(sW2 + kp * PITCH2 + tid);

        #pragma unroll
        for (int r = 0; r < BM; r++) {
            const double2* xr = (const double2*)(xn + r * P_ + kk);
            #pragma unroll
            for (int q = 0; q < KC / 4; q++) {        // 8 x LDS.128 broadcast
                double2 v = xr[q];
                ffma2(hacc2[r], v.x, wreg[2 * q]);
                ffma2(hacc2[r], v.y, wreg[2 * q + 1]);
            }
        }
        __syncthreads();
    }

    // ---------- Epilogue: ReLU, dot with W2, reduce, nan_to_num ----------------
    const float w2  = W2[tid];
    const float bb1 = b1[tid];
    #pragma unroll
    for (int r = 0; r < BM; r++) {
        float2 p = *reinterpret_cast<float2*>(&hacc2[r]);
        float h = p.x + p.y + bb1;
        h = fmaxf(h, 0.0f);
        float v = h * w2;
        #pragma unroll
        for (int o = 16; o > 0; o >>= 1) v += __shfl_xor_sync(0xffffffffu, v, o);
        if (lane == 0) red[r * 8 + wid] = v;
    }
    __syncthreads();

    if (tid < BM) {
        float y = b2[0];
        #pragma unroll
        for (int w = 0; w < 8; w++) y += red[tid * 8 + w];
        if (isnan(y)) y = 0.0f;
        else if (isinf(y)) y = (y > 0.0f) ? 3.4028234663852886e38f : -3.4028234663852886e38f;
        out[b0 + tid] = y;
    }
}

extern "C" void kernel_launch(void* const* d_in, const int* in_sizes, int n_in,
                              void* d_out, int out_size)
{
    const float* phys     = (const float*)d_in[0];
    const float* ratios   = (const float*)d_in[1];
    const int*   lengths  = (const int*)  d_in[2];
    const float* ln_gamma = (const float*)d_in[3];
    const float* ln_beta  = (const float*)d_in[4];
    const float* W1       = (const float*)d_in[5];
    const float* b1       = (const float*)d_in[6];
    const float* W2       = (const float*)d_in[7];
    const float* b2       = (const float*)d_in[8];
    float* out = (float*)d_out;

    const int smem_bytes = SMEM_FLOATS * (int)sizeof(float);
    cudaFuncSetAttribute(physchem_fused,
                         cudaFuncAttributeMaxDynamicSharedMemorySize, smem_bytes);

    dim3 grid(B_ / BM);
    dim3 block(NT);
    physchem_fused<<<grid, block, smem_bytes>>>(
        phys, ratios, lengths, ln_gamma, ln_beta, W1, b1, W2, b2, out);
}

// round 14
// speedup vs baseline: 1.8838x; 1.3285x over previous
#include <cuda_runtime.h>
#include <math.h>
#include <stdint.h>

#define B_   8192
#define F_   32
#define P_   512
#define H_   256
#define BM   16        // rows per CTA
#define KC   32        // K-chunk for W1 staging
#define NT   256       // threads per CTA

// sW4 layout: float4 sW4[j*9 + kq], j=0..255, kq=0..7 (pitch 9 float4 per j)
#define SW4_F4   (H_ * 9)            // 2304 float4 = 9216 floats

// smem (floats): xn 8192 + sW4 9216 + wnorm 512 + slen 16 + red 64
#define SMEM_FLOATS (BM * P_ + SW4_F4 * 4 + BM * F_ + BM + BM * 4)

// ---- cp.async 16B (L2-resident W1 -> smem, no register round-trip) ----
__device__ __forceinline__ void cp_async16(uint32_t dst_smem, const void* src) {
    asm volatile("cp.async.cg.shared.global [%0], [%1], 16;" :: "r"(dst_smem), "l"(src));
}
__device__ __forceinline__ void cp_commit() {
    asm volatile("cp.async.commit_group;" ::: "memory");
}
__device__ __forceinline__ void cp_wait0() {
    asm volatile("cp.async.wait_group 0;" ::: "memory");
}

// packed fp32x2 FMA
__device__ __forceinline__ void ffma2(double& acc, double x, double w) {
    asm("fma.rn.f32x2 %0, %1, %2, %0;"
        : "+l"(*reinterpret_cast<unsigned long long*>(&acc))
        : "l"(*reinterpret_cast<unsigned long long*>(&x)),
          "l"(*reinterpret_cast<unsigned long long*>(&w)));
}

__global__ __launch_bounds__(NT, 3)
void physchem_fused(const float* __restrict__ phys,
                    const float* __restrict__ ratios,
                    const int*   __restrict__ lengths,
                    const float* __restrict__ ln_gamma,
                    const float* __restrict__ ln_beta,
                    const float* __restrict__ W1,
                    const float* __restrict__ b1,
                    const float* __restrict__ W2,
                    const float* __restrict__ b2,
                    float*       __restrict__ out)
{
    extern __shared__ float sm[];
    float*  xn    = sm;                          // [BM][P_]
    float4* sW4   = (float4*)(sm + BM * P_);     // [256][9] float4
    float*  wnorm = sm + BM * P_ + SW4_F4 * 4;   // [BM][F_]
    int*    slen  = (int*)(wnorm + BM * F_);     // [BM]
    float*  red   = (float*)(slen + BM);         // [BM][4]

    const int tid  = threadIdx.x;
    const int wid  = tid >> 5;
    const int lane = tid & 31;
    const int b0   = blockIdx.x * BM;

    // ---------- A0: normalized weights + lengths (warp w -> rows 2w, 2w+1) ------
    #pragma unroll
    for (int rr = 0; rr < 2; rr++) {
        const int r = wid * 2 + rr;
        const int b = b0 + r;
        const int len = lengths[b];
        if (lane == 0) slen[r] = len;
        float rv = (lane < len) ? ratios[b * F_ + lane] : 0.0f;
        float s = rv;
        #pragma unroll
        for (int o = 16; o > 0; o >>= 1) s += __shfl_xor_sync(0xffffffffu, s, o);
        wnorm[r * F_ + lane] = rv / (s + 1e-8f);  // zero for lane >= len
    }
    __syncthreads();

    // ---------- A1: weighted mix, float4 loads, f unrolled x4 -------------------
    // warp w: p-quarter (w&3), row-half (w>>2). lane owns one float4 per row slice.
    {
        const int q  = wid & 3;
        const int rh = (wid >> 2) * 8;
        const int v4 = q * 32 + lane;             // float4 index within row (0..127)
        for (int rr = 0; rr < 8; rr++) {
            const int r   = rh + rr;
            const int len = slen[r];
            const float*  wr = wnorm + r * F_;
            const float4* pp = (const float4*)(phys + (size_t)(b0 + r) * (F_ * P_)) + v4;
            float4 acc = make_float4(0.f, 0.f, 0.f, 0.f);
            const int f4 = (len + 3) & ~3;        // wnorm zero-padded past len
            for (int f = 0; f < f4; f += 4) {
                const float w0 = wr[f + 0];
                const float w1 = wr[f + 1];
                const float w2_ = wr[f + 2];
                const float w3 = wr[f + 3];
                float4 u0 = pp[(f + 0) * (P_ / 4)];
                float4 u1 = pp[(f + 1) * (P_ / 4)];
                float4 u2 = pp[(f + 2) * (P_ / 4)];
                float4 u3 = pp[(f + 3) * (P_ / 4)];
                acc.x += w0*u0.x + w1*u1.x + w2_*u2.x + w3*u3.x;
                acc.y += w0*u0.y + w1*u1.y + w2_*u2.y + w3*u3.y;
                acc.z += w0*u0.z + w1*u1.z + w2_*u2.z + w3*u3.z;
                acc.w += w0*u0.w + w1*u1.w + w2_*u2.w + w3*u3.w;
            }
            ((float4*)(xn + r * P_))[v4] = acc;
        }
    }
    __syncthreads();

    // ---------- A2: LayerNorm in-place (warp w -> rows 2w, 2w+1) ----------------
    #pragma unroll
    for (int rr = 0; rr < 2; rr++) {
        const int r = wid * 2 + rr;
        float4 vv[4];
        float s = 0.0f, s2 = 0.0f;
        #pragma unroll
        for (int i = 0; i < 4; i++) {
            vv[i] = ((const float4*)(xn + r * P_))[lane + 32 * i];
            s  += vv[i].x + vv[i].y + vv[i].z + vv[i].w;
            s2 += vv[i].x * vv[i].x + vv[i].y * vv[i].y
                + vv[i].z * vv[i].z + vv[i].w * vv[i].w;
        }
        #pragma unroll
        for (int o = 16; o > 0; o >>= 1) {
            s  += __shfl_xor_sync(0xffffffffu, s,  o);
            s2 += __shfl_xor_sync(0xffffffffu, s2, o);
        }
        const float mu   = s * (1.0f / P_);
        const float var  = fmaxf(s2 * (1.0f / P_) - mu * mu, 0.0f);
        const float rstd = rsqrtf(var + 1e-5f);
        #pragma unroll
        for (int i = 0; i < 4; i++) {
            const int vi = lane + 32 * i;
            float4 g  = ((const float4*)ln_gamma)[vi];
            float4 be = ((const float4*)ln_beta)[vi];
            float4 o4;
            o4.x = (vv[i].x - mu) * rstd * g.x + be.x;
            o4.y = (vv[i].y - mu) * rstd * g.y + be.y;
            o4.z = (vv[i].z - mu) * rstd * g.z + be.z;
            o4.w = (vv[i].w - mu) * rstd * g.w + be.w;
            ((float4*)(xn + r * P_))[vi] = o4;
        }
    }

    // ---------- Phase B: x @ W1^T, 2 cols/thread, FFMA2 ------------------------
    // threads 0-127 -> rows 0-7, threads 128-255 -> rows 8-15
    // thread owns columns jt and jt+128.
    const int jt = tid & 127;
    const int r0 = (tid >> 7) * 8;

    uint32_t sW4_u32;
    asm("{ .reg .u64 t; cvta.to.shared.u64 t, %1; cvt.u32.u64 %0, t; }"
        : "=r"(sW4_u32) : "l"((const void*)sW4));

    double accA[8], accB[8];
    #pragma unroll
    for (int r = 0; r < 8; r++) { accA[r] = 0.0; accB[r] = 0.0; }

    const double2* sW4d = (const double2*)sW4;

    for (int c = 0; c < P_ / KC; c++) {           // 16 chunks
        const int kk = c * KC;
        __syncthreads();                          // previous compute done -> buf free
        // stage: 2048 float4 of W1 chunk via cp.async (8 per thread)
        #pragma unroll
        for (int t = 0; t < 8; t++) {
            const int idx = tid + t * NT;         // 0..2047
            const int j   = idx >> 3;             // 0..255
            const int kq  = idx & 7;              // 0..7
            cp_async16(sW4_u32 + (uint32_t)(j * 9 + kq) * 16u,
                       W1 + j * P_ + kk + kq * 4);
        }
        cp_commit();
        cp_wait0();
        __syncthreads();                          // all stages visible

        #pragma unroll
        for (int sub = 0; sub < 4; sub++) {       // 8 k per sub
            double2 wA0 = sW4d[jt * 9 + 2 * sub];
            double2 wA1 = sW4d[jt * 9 + 2 * sub + 1];
            double2 wB0 = sW4d[(jt + 128) * 9 + 2 * sub];
            double2 wB1 = sW4d[(jt + 128) * 9 + 2 * sub + 1];
            #pragma unroll
            for (int r = 0; r < 8; r++) {
                const double2* xr = (const double2*)(xn + (r0 + r) * P_ + kk + sub * 8);
                double2 x0 = xr[0];               // k pairs 0,1
                double2 x1 = xr[1];               // k pairs 2,3
                ffma2(accA[r], x0.x, wA0.x);
                ffma2(accA[r], x0.y, wA0.y);
                ffma2(accA[r], x1.x, wA1.x);
                ffma2(accA[r], x1.y, wA1.y);
                ffma2(accB[r], x0.x, wB0.x);
                ffma2(accB[r], x0.y, wB0.y);
                ffma2(accB[r], x1.x, wB1.x);
                ffma2(accB[r], x1.y, wB1.y);
            }
        }
    }

    // ---------- Epilogue: ReLU, dot with W2, reduce, nan_to_num ----------------
    const float w2A = W2[jt];
    const float w2B = W2[jt + 128];
    const float b1A = b1[jt];
    const float b1B = b1[jt + 128];
    #pragma unroll
    for (int r = 0; r < 8; r++) {
        float2 pa = *reinterpret_cast<float2*>(&accA[r]);
        float2 pb = *reinterpret_cast<float2*>(&accB[r]);
        float hA = fmaxf(pa.x + pa.y + b1A, 0.0f);
        float hB = fmaxf(pb.x + pb.y + b1B, 0.0f);
        float v = hA * w2A + hB * w2B;
        #pragma unroll
        for (int o = 16; o > 0; o >>= 1) v += __shfl_xor_sync(0xffffffffu, v, o);
        if (lane == 0) red[(r0 + r) * 4 + (wid & 3)] = v;
    }
    __syncthreads();

    if (tid < BM) {
        float y = b2[0];
        #pragma unroll
        for (int w = 0; w < 4; w++) y += red[tid * 4 + w];
        if (isnan(y)) y = 0.0f;
        else if (isinf(y)) y = (y > 0.0f) ? 3.4028234663852886e38f : -3.4028234663852886e38f;
        out[b0 + tid] = y;
    }
}

extern "C" void kernel_launch(void* const* d_in, const int* in_sizes, int n_in,
                              void* d_out, int out_size)
{
    const float* phys     = (const float*)d_in[0];
    const float* ratios   = (const float*)d_in[1];
    const int*   lengths  = (const int*)  d_in[2];
    const float* ln_gamma = (const float*)d_in[3];
    const float* ln_beta  = (const float*)d_in[4];
    const float* W1       = (const float*)d_in[5];
    const float* b1       = (const float*)d_in[6];
    const float* W2       = (const float*)d_in[7];
    const float* b2       = (const float*)d_in[8];
    float* out = (float*)d_out;

    const int smem_bytes = SMEM_FLOATS * (int)sizeof(float);
    cudaFuncSetAttribute(physchem_fused,
                         cudaFuncAttributeMaxDynamicSharedMemorySize, smem_bytes);

    dim3 grid(B_ / BM);
    dim3 block(NT);
    physchem_fused<<<grid, block, smem_bytes>>>(
        phys, ratios, lengths, ln_gamma, ln_beta, W1, b1, W2, b2, out);
}

// round 15
// speedup vs baseline: 1.9015x; 1.0094x over previous
#include <cuda_runtime.h>
#include <math.h>
#include <stdint.h>

#define B_   8192
#define F_   32
#define P_   512
#define H_   256
#define BM   16        // rows per CTA
#define KC   32        // K-chunk for W1 staging (phase B)
#define NT   256       // threads per CTA

// ---- phase A ring: 4 slots x 8 KB (4 fragments of one row per chunk) ----
#define NSLOT       4
#define SLOT_FLOATS (4 * P_)              // 2048 floats = 8 KB
// ---- phase B W1 tile: float4 sW4[j*9 + kq] ----
#define SW4_F4      (H_ * 9)              // 2304 float4 = 9216 floats
#define UNI_FLOATS  (SW4_F4 * 4)          // 9216 floats (>= ring 8192)

// smem layout (floats)
#define OFF_XN     0
#define OFF_UNI    (BM * P_)              // 8192
#define OFF_WNORM  (OFF_UNI + UNI_FLOATS) // 17408
#define OFF_SLEN   (OFF_WNORM + BM * F_)  // 17920 (ints)
#define OFF_RED    (OFF_SLEN + BM)        // 17936
#define OFF_CLIST  (OFF_RED + BM * 4)     // 18000 (ints, max 128 chunks)
#define OFF_NCH    (OFF_CLIST + 128)      // 18128 (int)
#define OFF_MBAR   (OFF_NCH + 2)          // 18130 (even -> 8B aligned); 16 floats
#define SMEM_FLOATS (OFF_MBAR + 16)       // 18146 floats = 72.6 KB

// ---- mbarrier / bulk-copy helpers ----
__device__ __forceinline__ void mbar_init(uint32_t mbar, uint32_t count) {
    asm volatile("mbarrier.init.shared.b64 [%0], %1;" :: "r"(mbar), "r"(count) : "memory");
}
__device__ __forceinline__ void mbar_expect_tx(uint32_t mbar, uint32_t bytes) {
    asm volatile("mbarrier.arrive.expect_tx.shared.b64 _, [%0], %1;"
                 :: "r"(mbar), "r"(bytes) : "memory");
}
__device__ __forceinline__ void mbar_arrive(uint32_t mbar) {
    asm volatile("mbarrier.arrive.shared.b64 _, [%0];" :: "r"(mbar) : "memory");
}
__device__ __forceinline__ void mbar_wait(uint32_t mbar, uint32_t parity) {
    asm volatile(
        "{\n\t.reg .pred P;\n\t"
        "W_%=:\n\t"
        "mbarrier.try_wait.parity.acquire.cta.shared::cta.b64 P, [%0], %1, 0x989680;\n\t"
        "@!P bra W_%=;\n\t}"
        :: "r"(mbar), "r"(parity) : "memory");
}
__device__ __forceinline__ void bulk_g2s(uint32_t dst, const void* src,
                                         uint32_t bytes, uint32_t mbar) {
    asm volatile(
        "cp.async.bulk.shared::cluster.global.mbarrier::complete_tx::bytes "
        "[%0], [%1], %2, [%3];"
        :: "r"(dst), "l"(src), "r"(bytes), "r"(mbar) : "memory");
}

// ---- cp.async 16B for W1 staging (phase B, unchanged from R14) ----
__device__ __forceinline__ void cp_async16(uint32_t dst_smem, const void* src) {
    asm volatile("cp.async.cg.shared.global [%0], [%1], 16;" :: "r"(dst_smem), "l"(src));
}
__device__ __forceinline__ void cp_commit() {
    asm volatile("cp.async.commit_group;" ::: "memory");
}
__device__ __forceinline__ void cp_wait0() {
    asm volatile("cp.async.wait_group 0;" ::: "memory");
}

// packed fp32x2 FMA
__device__ __forceinline__ void ffma2(double& acc, double x, double w) {
    asm("fma.rn.f32x2 %0, %1, %2, %0;"
        : "+l"(*reinterpret_cast<unsigned long long*>(&acc))
        : "l"(*reinterpret_cast<unsigned long long*>(&x)),
          "l"(*reinterpret_cast<unsigned long long*>(&w)));
}

__global__ __launch_bounds__(NT, 3)
void physchem_fused(const float* __restrict__ phys,
                    const float* __restrict__ ratios,
                    const int*   __restrict__ lengths,
                    const float* __restrict__ ln_gamma,
                    const float* __restrict__ ln_beta,
                    const float* __restrict__ W1,
                    const float* __restrict__ b1,
                    const float* __restrict__ W2,
                    const float* __restrict__ b2,
                    float*       __restrict__ out)
{
    extern __shared__ float sm[];
    float*  xn    = sm + OFF_XN;
    float*  ring  = sm + OFF_UNI;
    float4* sW4   = (float4*)(sm + OFF_UNI);
    float*  wnorm = sm + OFF_WNORM;
    int*    slen  = (int*)(sm + OFF_SLEN);
    float*  red   = sm + OFF_RED;
    int*    clist = (int*)(sm + OFF_CLIST);
    int*    nchp  = (int*)(sm + OFF_NCH);

    const int tid  = threadIdx.x;
    const int wid  = tid >> 5;
    const int lane = tid & 31;
    const int b0   = blockIdx.x * BM;

    uint32_t smem_u32;
    asm("{ .reg .u64 t; cvta.to.shared.u64 t, %1; cvt.u32.u64 %0, t; }"
        : "=r"(smem_u32) : "l"((const void*)sm));
    const uint32_t ring_u32 = smem_u32 + OFF_UNI * 4;
    const uint32_t mb       = smem_u32 + OFF_MBAR * 4;
    // full[s] = mb + 8s ; empty[s] = mb + 32 + 8s

    // ---------- A0: normalized weights + lengths (warp w -> rows 2w, 2w+1) ------
    #pragma unroll
    for (int rr = 0; rr < 2; rr++) {
        const int r = wid * 2 + rr;
        const int b = b0 + r;
        const int len = lengths[b];
        if (lane == 0) slen[r] = len;
        float rv = (lane < len) ? ratios[b * F_ + lane] : 0.0f;
        float s = rv;
        #pragma unroll
        for (int o = 16; o > 0; o >>= 1) s += __shfl_xor_sync(0xffffffffu, s, o);
        wnorm[r * F_ + lane] = rv / (s + 1e-8f);
    }
    __syncthreads();

    // ---------- A0b: chunk list (warp 0) + mbarrier init (tid 0) ----------------
    if (wid == 0) {
        const int len = (lane < BM) ? slen[lane] : 0;
        const int cnt = (len + 3) >> 2;               // chunks of up to 4 frags
        int inc = cnt;
        #pragma unroll
        for (int o = 1; o < 32; o <<= 1) {
            int u = __shfl_up_sync(0xffffffffu, inc, o);
            if (lane >= o) inc += u;
        }
        const int total = __shfl_sync(0xffffffffu, inc, 31);
        const int off   = inc - cnt;
        for (int c = 0; c < cnt; c++)
            clist[off + c] = (lane << 8) | (c * 4);   // (row, f0)
        if (lane == 0) *nchp = total;
    }
    if (tid == 0) {
        #pragma unroll
        for (int s = 0; s < NSLOT; s++) {
            mbar_init(mb + s * 8, 1);            // full: 1 arrival (expect_tx)
            mbar_init(mb + 32 + s * 8, NT);      // empty: all threads arrive
        }
    }
    __syncthreads();

    // ---------- A1: bulk-DMA pipelined weighted mix -----------------------------
    // Thread owns float2 column 2*tid of EVERY row. tid0 = producer (lookahead 3).
    {
        const int n = *nchp;                     // 16..128

        auto issue_chunk = [&](int k) {
            const int e  = clist[k];
            const int r  = e >> 8, f0 = e & 255;
            const int nf = min(4, slen[r] - f0);
            const uint32_t bytes = (uint32_t)nf * (P_ * 4);
            const uint32_t fullb = mb + (uint32_t)(k & 3) * 8;
            mbar_expect_tx(fullb, bytes);
            bulk_g2s(ring_u32 + (uint32_t)(k & 3) * (SLOT_FLOATS * 4),
                     phys + ((size_t)(b0 + r) * F_ + f0) * P_, bytes, fullb);
        };

        if (tid == 0) {
            issue_chunk(0); issue_chunk(1); issue_chunk(2);
        }

        int   cur_r = 0;
        float ax = 0.0f, ay = 0.0f;

        for (int i = 0; i < n; i++) {
            if (tid == 0 && i + 3 < n) {
                const int k = i + 3;
                // producer empty-wait: parity starts at 1 (first cycle passes)
                mbar_wait(mb + 32 + (uint32_t)(k & 3) * 8, (((k >> 2) & 1) ^ 1));
                issue_chunk(k);
            }
            const uint32_t s = (uint32_t)(i & 3);
            mbar_wait(mb + s * 8, (i >> 2) & 1);          // consumer full-wait

            const int e  = clist[i];
            const int r  = e >> 8, f0 = e & 255;
            const int nf = min(4, slen[r] - f0);
            if (r != cur_r) {
                *(float2*)(xn + cur_r * P_ + 2 * tid) = make_float2(ax, ay);
                ax = 0.0f; ay = 0.0f;
                cur_r = r;
            }
            const float* base = ring + s * SLOT_FLOATS + 2 * tid;
            for (int j = 0; j < nf; j++) {
                const float w = wnorm[r * F_ + f0 + j];   // warp-uniform broadcast
                float2 v = *(const float2*)(base + j * P_);
                ax += w * v.x;
                ay += w * v.y;
            }
            mbar_arrive(mb + 32 + s * 8);                 // consumer empty-arrive
        }
        *(float2*)(xn + cur_r * P_ + 2 * tid) = make_float2(ax, ay);
    }
    __syncthreads();

    // ---------- A2: LayerNorm in-place (warp w -> rows 2w, 2w+1) ----------------
    #pragma unroll
    for (int rr = 0; rr < 2; rr++) {
        const int r = wid * 2 + rr;
        float4 vv[4];
        float s = 0.0f, s2 = 0.0f;
        #pragma unroll
        for (int i = 0; i < 4; i++) {
            vv[i] = ((const float4*)(xn + r * P_))[lane + 32 * i];
            s  += vv[i].x + vv[i].y + vv[i].z + vv[i].w;
            s2 += vv[i].x * vv[i].x + vv[i].y * vv[i].y
                + vv[i].z * vv[i].z + vv[i].w * vv[i].w;
        }
        #pragma unroll
        for (int o = 16; o > 0; o >>= 1) {
            s  += __shfl_xor_sync(0xffffffffu, s,  o);
            s2 += __shfl_xor_sync(0xffffffffu, s2, o);
        }
        const float mu   = s * (1.0f / P_);
        const float var  = fmaxf(s2 * (1.0f / P_) - mu * mu, 0.0f);
        const float rstd = rsqrtf(var + 1e-5f);
        #pragma unroll
        for (int i = 0; i < 4; i++) {
            const int vi = lane + 32 * i;
            float4 g  = ((const float4*)ln_gamma)[vi];
            float4 be = ((const float4*)ln_beta)[vi];
            float4 o4;
            o4.x = (vv[i].x - mu) * rstd * g.x + be.x;
            o4.y = (vv[i].y - mu) * rstd * g.y + be.y;
            o4.z = (vv[i].z - mu) * rstd * g.z + be.z;
            o4.w = (vv[i].w - mu) * rstd * g.w + be.w;
            ((float4*)(xn + r * P_))[vi] = o4;
        }
    }

    // ---------- Phase B: x @ W1^T, 2 cols/thread, FFMA2 (R14 verbatim) ----------
    const int jt = tid & 127;
    const int r0 = (tid >> 7) * 8;
    const uint32_t sW4_u32 = smem_u32 + OFF_UNI * 4;

    double accA[8], accB[8];
    #pragma unroll
    for (int r = 0; r < 8; r++) { accA[r] = 0.0; accB[r] = 0.0; }

    const double2* sW4d = (const double2*)sW4;

    for (int c = 0; c < P_ / KC; c++) {           // 16 chunks
        const int kk = c * KC;
        __syncthreads();                          // prev compute done / ring free
        #pragma unroll
        for (int t = 0; t < 8; t++) {
            const int idx = tid + t * NT;         // 0..2047
            const int j   = idx >> 3;             // 0..255
            const int kq  = idx & 7;              // 0..7
            cp_async16(sW4_u32 + (uint32_t)(j * 9 + kq) * 16u,
                       W1 + j * P_ + kk + kq * 4);
        }
        cp_commit();
        cp_wait0();
        __syncthreads();

        #pragma unroll
        for (int sub = 0; sub < 4; sub++) {       // 8 k per sub
            double2 wA0 = sW4d[jt * 9 + 2 * sub];
            double2 wA1 = sW4d[jt * 9 + 2 * sub + 1];
            double2 wB0 = sW4d[(jt + 128) * 9 + 2 * sub];
            double2 wB1 = sW4d[(jt + 128) * 9 + 2 * sub + 1];
            #pragma unroll
            for (int r = 0; r < 8; r++) {
                const double2* xr = (const double2*)(xn + (r0 + r) * P_ + kk + sub * 8);
                double2 x0 = xr[0];
                double2 x1 = xr[1];
                ffma2(accA[r], x0.x, wA0.x);
                ffma2(accA[r], x0.y, wA0.y);
                ffma2(accA[r], x1.x, wA1.x);
                ffma2(accA[r], x1.y, wA1.y);
                ffma2(accB[r], x0.x, wB0.x);
                ffma2(accB[r], x0.y, wB0.y);
                ffma2(accB[r], x1.x, wB1.x);
                ffma2(accB[r], x1.y, wB1.y);
            }
        }
    }

    // ---------- Epilogue: ReLU, dot with W2, reduce, nan_to_num ----------------
    const float w2A = W2[jt];
    const float w2B = W2[jt + 128];
    const float b1A = b1[jt];
    const float b1B = b1[jt + 128];
    #pragma unroll
    for (int r = 0; r < 8; r++) {
        float2 pa = *reinterpret_cast<float2*>(&accA[r]);
        float2 pb = *reinterpret_cast<float2*>(&accB[r]);
        float hA = fmaxf(pa.x + pa.y + b1A, 0.0f);
        float hB = fmaxf(pb.x + pb.y + b1B, 0.0f);
        float v = hA * w2A + hB * w2B;
        #pragma unroll
        for (int o = 16; o > 0; o >>= 1) v += __shfl_xor_sync(0xffffffffu, v, o);
        if (lane == 0) red[(r0 + r) * 4 + (wid & 3)] = v;
    }
    __syncthreads();

    if (tid < BM) {
        float y = b2[0];
        #pragma unroll
        for (int w = 0; w < 4; w++) y += red[tid * 4 + w];
        if (isnan(y)) y = 0.0f;
        else if (isinf(y)) y = (y > 0.0f) ? 3.4028234663852886e38f : -3.4028234663852886e38f;
        out[b0 + tid] = y;
    }
}

extern "C" void kernel_launch(void* const* d_in, const int* in_sizes, int n_in,
                              void* d_out, int out_size)
{
    const float* phys     = (const float*)d_in[0];
    const float* ratios   = (const float*)d_in[1];
    const int*   lengths  = (const int*)  d_in[2];
    const float* ln_gamma = (const float*)d_in[3];
    const float* ln_beta  = (const float*)d_in[4];
    const float* W1       = (const float*)d_in[5];
    const float* b1       = (const float*)d_in[6];
    const float* W2       = (const float*)d_in[7];
    const float* b2       = (const float*)d_in[8];
    float* out = (float*)d_out;

    const int smem_bytes = SMEM_FLOATS * (int)sizeof(float);
    cudaFuncSetAttribute(physchem_fused,
                         cudaFuncAttributeMaxDynamicSharedMemorySize, smem_bytes);

    dim3 grid(B_ / BM);
    dim3 block(NT);
    physchem_fused<<<grid, block, smem_bytes>>>(
        phys, ratios, lengths, ln_gamma, ln_beta, W1, b1, W2, b2, out);
}